// round 2
// baseline (speedup 1.0000x reference)
#include <cuda_runtime.h>
#include <cstdint>

// ---------------------------------------------------------------------------
// Problem constants (shapes fixed by setup_inputs: N=200000, D=128, P=10)
// ---------------------------------------------------------------------------
#define DDIM      128
#define NMAXPAD   200704          // >= ceil(200000/256)*256
#define NBMAX     784             // NMAXPAD/256

// ---------------------------------------------------------------------------
// Static device scratch (no allocations allowed)
// ---------------------------------------------------------------------------
__device__ unsigned g_keysA[NMAXPAD];
__device__ unsigned g_keysB[NMAXPAD];
__device__ unsigned g_hist  [256 * NBMAX];
__device__ unsigned g_prefix[256 * NBMAX];
__device__ unsigned g_digitTotal[256];
__device__ unsigned g_digitBase[256];
__device__ double   g_xs[NMAXPAD + 2];       // 1-based sorted values (double)
__device__ int      g_mn[NMAXPAD + 2];
__device__ int      g_mj[NMAXPAD + 2];
__device__ int      g_gcm[NMAXPAD + 2];
__device__ int      g_lcm[NMAXPAD + 2];
__device__ int      g_stackA[NMAXPAD + 2];
__device__ int      g_stackB[NMAXPAD + 2];
__device__ double   g_xstackA[NMAXPAD + 2];
__device__ double   g_xstackB[NMAXPAD + 2];

// ---------------------------------------------------------------------------
// 1) Projection: x_proj[i] = dot(X[i,:], p)  (warp per row), write sortable key
// key transform: b>=0 -> b|0x80000000 ; b<0 -> ~b   (ascending uint == ascending float)
// ---------------------------------------------------------------------------
__global__ void proj_kernel(const float* __restrict__ X,
                            const float* __restrict__ P,
                            const int* __restrict__ idx,
                            int N, int NPAD)
{
    int gtid   = blockIdx.x * blockDim.x + threadIdx.x;
    int warpId = gtid >> 5;
    int lane   = threadIdx.x & 31;

    const float4* p4 = (const float4*)(P + (size_t)(*idx) * DDIM);
    float4 pv = p4[lane];

    if (warpId < N) {
        const float4* x4 = (const float4*)(X + (size_t)warpId * DDIM);
        float4 xv = x4[lane];
        float s = xv.x * pv.x + xv.y * pv.y + xv.z * pv.z + xv.w * pv.w;
        #pragma unroll
        for (int off = 16; off; off >>= 1)
            s += __shfl_xor_sync(0xffffffffu, s, off);
        if (lane == 0) {
            unsigned b = __float_as_uint(s);
            g_keysA[warpId] = (b & 0x80000000u) ? ~b : (b | 0x80000000u);
        }
    }
    // pad tail with +inf keys so they sort to the end
    if (gtid < NPAD - N) g_keysA[N + gtid] = 0xFFFFFFFFu;
}

// ---------------------------------------------------------------------------
// 2) Radix sort: 4 passes x 8 bits, ping-pong A<->B (ends in A after 4 passes)
// ---------------------------------------------------------------------------
__global__ void hist_kernel(int srcIsA, int shift, int NB)
{
    const unsigned* in = srcIsA ? g_keysA : g_keysB;
    __shared__ unsigned sh[256];
    sh[threadIdx.x] = 0;
    __syncthreads();
    unsigned key = in[blockIdx.x * 256 + threadIdx.x];
    atomicAdd(&sh[(key >> shift) & 255u], 1u);
    __syncthreads();
    g_hist[threadIdx.x * NB + blockIdx.x] = sh[threadIdx.x];
}

__global__ void scan_digit_kernel(int NB)
{
    int d = blockIdx.x;
    int t = threadIdx.x;
    __shared__ unsigned sh[256];
    __shared__ unsigned s_tot;
    unsigned carry = 0;
    for (int base = 0; base < NB; base += 256) {
        int i = base + t;
        unsigned v = (i < NB) ? g_hist[d * NB + i] : 0u;
        sh[t] = v;
        __syncthreads();
        unsigned x = v;
        #pragma unroll
        for (int off = 1; off < 256; off <<= 1) {
            unsigned y = (t >= off) ? sh[t - off] : 0u;
            __syncthreads();
            if (t >= off) x += y;
            sh[t] = x;
            __syncthreads();
        }
        if (i < NB) g_prefix[d * NB + i] = carry + x - v;
        if (t == 255) s_tot = x;
        __syncthreads();
        carry += s_tot;
        __syncthreads();
    }
    if (t == 0) g_digitTotal[d] = carry;
}

__global__ void scan_base_kernel()
{
    int t = threadIdx.x;
    __shared__ unsigned sh[256];
    unsigned v = g_digitTotal[t];
    sh[t] = v;
    __syncthreads();
    unsigned x = v;
    #pragma unroll
    for (int off = 1; off < 256; off <<= 1) {
        unsigned y = (t >= off) ? sh[t - off] : 0u;
        __syncthreads();
        if (t >= off) x += y;
        sh[t] = x;
        __syncthreads();
    }
    g_digitBase[t] = x - v;  // exclusive
}

__global__ void scatter_kernel(int srcIsA, int shift, int NB)
{
    const unsigned* in  = srcIsA ? g_keysA : g_keysB;
    unsigned*       out = srcIsA ? g_keysB : g_keysA;
    __shared__ unsigned warpHist[8][256];
    int t = threadIdx.x, w = t >> 5, lane = t & 31;
    for (int i = t; i < 8 * 256; i += 256) ((unsigned*)warpHist)[i] = 0u;
    __syncthreads();

    unsigned key = in[blockIdx.x * 256 + t];
    unsigned d   = (key >> shift) & 255u;
    unsigned peers = __match_any_sync(0xffffffffu, d);
    unsigned rank  = __popc(peers & ((1u << lane) - 1u));
    int leader = __ffs(peers) - 1;
    if (lane == leader) warpHist[w][d] = __popc(peers);
    __syncthreads();

    unsigned base = 0;
    for (int w2 = 0; w2 < w; ++w2) base += warpHist[w2][d];
    unsigned pos = g_digitBase[d] + g_prefix[d * NB + blockIdx.x] + base + rank;
    out[pos] = key;
}

// ---------------------------------------------------------------------------
// 3) Finalize: inverse key transform, store sorted doubles 1-based in g_xs
// ---------------------------------------------------------------------------
__global__ void finalize_kernel(int N)
{
    int i = blockIdx.x * blockDim.x + threadIdx.x;
    if (i == 0) g_xs[0] = 0.0;
    if (i < N) {
        unsigned k = g_keysA[i];
        unsigned b = (k & 0x80000000u) ? (k ^ 0x80000000u) : ~k;
        g_xs[i + 1] = (double)__uint_as_float(b);
    }
}

// ---------------------------------------------------------------------------
// 4) Dip kernel: single block, 512 threads.
//    Stage 1: mn (thread 0) & mj (thread 32, other warp) via explicit stacks.
//    Stage 2: Hartigan outer loop; chain walk on tid 0, segment argmax scans
//             cooperative across the block (only the max VALUE matters).
// ---------------------------------------------------------------------------
__global__ void __launch_bounds__(512, 1) dip_kernel(float* out, int N)
{
    const double* xs = g_xs;  // 1-based
    int tid = threadIdx.x;

    __shared__ int    s_early;
    if (tid == 0) s_early = (N < 4 || xs[1] == xs[N]) ? 1 : 0;
    __syncthreads();
    if (s_early) {
        if (tid == 0) out[0] = (float)(1.0 / (2.0 * (double)(N > 1 ? N : 1)));
        return;
    }

    // ---- Stage 1: hull pointer arrays (two concurrent warps) ----
    if (tid == 0) {
        int*    st = g_stackA;
        double* xv = g_xstackA;
        int sp = 0;
        st[sp] = 1; xv[sp] = xs[1]; ++sp;
        g_mn[1] = 1;
        double x_top = xs[1], x_below = 0.0;
        for (int j = 2; j <= N; ++j) {
            double xj = xs[j];
            while (sp >= 2) {
                int top = st[sp - 1], below = st[sp - 2];
                if ((xj - x_top) * (double)(top - below) <
                    (x_top - x_below) * (double)(j - top)) break;
                --sp;
                x_top = x_below;
                x_below = (sp >= 2) ? xv[sp - 2] : 0.0;
            }
            g_mn[j] = st[sp - 1];
            st[sp] = j; xv[sp] = xj; ++sp;
            x_below = x_top; x_top = xj;
        }
    } else if (tid == 32) {
        int*    st = g_stackB;
        double* xv = g_xstackB;
        int sp = 0;
        st[sp] = N; xv[sp] = xs[N]; ++sp;
        g_mj[N] = N;
        double x_top = xs[N], x_below = 0.0;
        for (int k = N - 1; k >= 1; --k) {
            double xk = xs[k];
            while (sp >= 2) {
                int top = st[sp - 1], below = st[sp - 2];
                if ((xk - x_top) * (double)(top - below) <
                    (x_top - x_below) * (double)(k - top)) break;
                --sp;
                x_top = x_below;
                x_below = (sp >= 2) ? xv[sp - 2] : 0.0;
            }
            g_mj[k] = st[sp - 1];
            st[sp] = k; xv[sp] = xk; ++sp;
            x_below = x_top; x_top = xk;
        }
    }
    __syncthreads();

    // ---- Stage 2: Hartigan outer loop ----
    __shared__ double sh_red[512];
    __shared__ int    s_ig, s_ih, s_lgcm, s_llcm, s_low, s_high, s_break;
    __shared__ double s_d, s_dip;

    if (tid == 0) { s_low = 1; s_high = N; s_dip = 1.0; }
    __syncthreads();

    while (true) {
        __syncthreads();  // protect shared writes below vs laggard readers
        if (tid == 0) {
            int low = s_low, high = s_high;
            // gcm chain
            g_gcm[1] = high;
            int i = 1;
            while (g_gcm[i] > low) { g_gcm[i + 1] = g_mn[g_gcm[i]]; ++i; }
            int ig = i, l_gcm = i;
            int ix = ig - 1;
            // lcm chain
            g_lcm[1] = low;
            i = 1;
            while (g_lcm[i] < high) { g_lcm[i + 1] = g_mj[g_lcm[i]]; ++i; }
            int ih = i, l_lcm = i;
            int iv = 2;
            double d = 0.0;
            if (l_gcm != 2 || l_lcm != 2) {
                while (true) {
                    int gcmix = g_gcm[ix], lcmiv = g_lcm[iv];
                    if (gcmix > lcmiv) {
                        int gcmi1 = g_gcm[ix + 1];
                        double t = ((double)lcmiv - (double)gcmi1 + 1.0)
                                 - (xs[lcmiv] - xs[gcmi1]) * (double)(gcmix - gcmi1)
                                   / (xs[gcmix] - xs[gcmi1]);
                        ++iv;
                        if (t >= d) { d = t; ig = ix + 1; ih = iv - 1; }
                    } else {
                        int lcmiv1 = g_lcm[iv - 1];
                        double t = (xs[gcmix] - xs[lcmiv1]) * (double)(lcmiv - lcmiv1)
                                   / (xs[lcmiv] - xs[lcmiv1])
                                 - ((double)gcmix - (double)lcmiv1 - 1.0);
                        --ix;
                        if (t > d) { d = t; ig = ix + 1; ih = iv; }
                    }
                    if (ix < 1) ix = 1;
                    if (iv > l_lcm) iv = l_lcm;
                    if (g_gcm[ix] == g_lcm[iv]) break;
                }
            } else {
                d = 1.0;
            }
            s_d = d; s_ig = ig; s_ih = ih; s_lgcm = l_gcm; s_llcm = l_lcm;
            s_break = (d < s_dip) ? 1 : 0;
        }
        __syncthreads();
        if (s_break) break;

        // dip of the convex minorant (cooperative argmax per segment)
        double dip_l = 0.0;
        for (int j = s_ig; j < s_lgcm; ++j) {
            int jb = g_gcm[j + 1], je = g_gcm[j];
            double max_t = 1.0;
            if (je - jb > 1 && xs[je] != xs[jb]) {
                double C = (double)(je - jb) / (xs[je] - xs[jb]);
                double xjb = xs[jb];
                double local = -1e300;
                for (int i2 = tid; i2 <= je - jb; i2 += 512) {
                    double t = ((double)i2 + 1.0) - (xs[jb + i2] - xjb) * C;
                    if (t > local) local = t;
                }
                sh_red[tid] = local;
                __syncthreads();
                #pragma unroll
                for (int off = 256; off >= 1; off >>= 1) {
                    if (tid < off) {
                        double o = sh_red[tid + off];
                        if (o > sh_red[tid]) sh_red[tid] = o;
                    }
                    __syncthreads();
                }
                double segmax = sh_red[0];
                __syncthreads();
                if (segmax > max_t) max_t = segmax;
            }
            if (dip_l < max_t) dip_l = max_t;
        }

        // dip of the concave majorant
        double dip_u = 0.0;
        for (int j = s_ih; j < s_llcm; ++j) {
            int jb = g_lcm[j], je = g_lcm[j + 1];
            double max_t = 1.0;
            if (je - jb > 1 && xs[je] != xs[jb]) {
                double C = (double)(je - jb) / (xs[je] - xs[jb]);
                double xjb = xs[jb];
                double local = -1e300;
                for (int i2 = tid; i2 <= je - jb; i2 += 512) {
                    double t = (xs[jb + i2] - xjb) * C - ((double)i2 - 1.0);
                    if (t > local) local = t;
                }
                sh_red[tid] = local;
                __syncthreads();
                #pragma unroll
                for (int off = 256; off >= 1; off >>= 1) {
                    if (tid < off) {
                        double o = sh_red[tid + off];
                        if (o > sh_red[tid]) sh_red[tid] = o;
                    }
                    __syncthreads();
                }
                double segmax = sh_red[0];
                __syncthreads();
                if (segmax > max_t) max_t = segmax;
            }
            if (dip_u < max_t) dip_u = max_t;
        }

        if (tid == 0) {
            double dip_new = (dip_u > dip_l) ? dip_u : dip_l;
            if (s_dip < dip_new) s_dip = dip_new;
            int nlow = g_gcm[s_ig], nhigh = g_lcm[s_ih];
            if (s_low == nlow && s_high == nhigh) {
                s_break = 1;
            } else {
                s_low = nlow; s_high = nhigh; s_break = 0;
            }
        }
        __syncthreads();
        if (s_break) break;
    }

    if (tid == 0) out[0] = (float)(s_dip / (2.0 * (double)N));
}

// ---------------------------------------------------------------------------
// kernel_launch
// ---------------------------------------------------------------------------
extern "C" void kernel_launch(void* const* d_in, const int* in_sizes, int n_in,
                              void* d_out, int out_size)
{
    const float* X   = (const float*)d_in[0];
    const float* P   = (const float*)d_in[1];
    const int*   idx = (const int*)d_in[2];
    float*       out = (float*)d_out;

    int N    = in_sizes[0] / DDIM;
    int NB   = (N + 255) / 256;
    int NPAD = NB * 256;

    // 1) projection + key transform + padding
    proj_kernel<<<(N + 7) / 8, 256>>>(X, P, idx, N, NPAD);

    // 2) radix sort, 4 passes of 8 bits (A->B->A->B->A)
    int srcIsA = 1;
    for (int pass = 0; pass < 4; ++pass) {
        int shift = pass * 8;
        hist_kernel<<<NB, 256>>>(srcIsA, shift, NB);
        scan_digit_kernel<<<256, 256>>>(NB);
        scan_base_kernel<<<1, 256>>>();
        scatter_kernel<<<NB, 256>>>(srcIsA, shift, NB);
        srcIsA ^= 1;
    }

    // 3) sorted keys -> double xs[1..N]
    finalize_kernel<<<(N + 255) / 256, 256>>>(N);

    // 4) dip statistic
    dip_kernel<<<1, 512>>>(out, N);
}

// round 3
// speedup vs baseline: 16.0190x; 16.0190x over previous
#include <cuda_runtime.h>
#include <cstdint>

// ---------------------------------------------------------------------------
// Problem constants (shapes fixed by setup_inputs: N=200000, D=128, P=10)
// ---------------------------------------------------------------------------
#define DDIM      128
#define NMAXPAD   200704          // >= ceil(200000/256)*256
#define NBMAX     784             // NMAXPAD/256

#define CHUNKS    2048            // L1 chunks per hull
#define CAP       104             // per-chunk candidate cap (ceil(200000/2048)=98)
#define L2GROUPS  32
#define CHPERGRP  (CHUNKS / L2GROUPS)      // 64
#define L2STRIDE  (CHPERGRP * CAP)         // 6656
#define MAXIT     48

// ---------------------------------------------------------------------------
// Static device scratch (no allocations allowed)
// ---------------------------------------------------------------------------
__device__ unsigned g_keysA[NMAXPAD];
__device__ unsigned g_keysB[NMAXPAD];
__device__ unsigned g_hist  [256 * NBMAX];
__device__ unsigned g_prefix[256 * NBMAX];
__device__ unsigned g_digitTotal[256];
__device__ unsigned g_digitBase[256];
__device__ double   g_xs[NMAXPAD + 2];       // 1-based sorted values (double)

// hull scratch
__device__ int g_candLo[CHUNKS * CAP];
__device__ int g_candUp[CHUNKS * CAP];
__device__ int g_candCntLo[CHUNKS];
__device__ int g_candCntUp[CHUNKS];
__device__ int g_l2Lo[L2GROUPS * L2STRIDE];
__device__ int g_l2Up[L2GROUPS * L2STRIDE];
__device__ int g_l2CntLo[L2GROUPS];
__device__ int g_l2CntUp[L2GROUPS];
__device__ int g_hullLo[NMAXPAD + 2];
__device__ int g_hullUp[NMAXPAD + 2];
__device__ int g_gcm[NMAXPAD + 2];
__device__ int g_lcm[NMAXPAD + 2];
__device__ double g_segCLo[NMAXPAD + 2];
__device__ double g_segCUp[NMAXPAD + 2];

// dip iteration state
__device__ int    g_low, g_high, g_done;
__device__ int    g_ig, g_ih, g_lgcm, g_llcm;
__device__ double g_dip;
__device__ unsigned long long g_scanmax;

// ---------------------------------------------------------------------------
// 1) Projection: x_proj[i] = dot(X[i,:], p)  (warp per row), write sortable key
// ---------------------------------------------------------------------------
__global__ void proj_kernel(const float* __restrict__ X,
                            const float* __restrict__ P,
                            const int* __restrict__ idx,
                            int N, int NPAD)
{
    int gtid   = blockIdx.x * blockDim.x + threadIdx.x;
    int warpId = gtid >> 5;
    int lane   = threadIdx.x & 31;

    const float4* p4 = (const float4*)(P + (size_t)(*idx) * DDIM);
    float4 pv = p4[lane];

    if (warpId < N) {
        const float4* x4 = (const float4*)(X + (size_t)warpId * DDIM);
        float4 xv = x4[lane];
        float s = xv.x * pv.x + xv.y * pv.y + xv.z * pv.z + xv.w * pv.w;
        #pragma unroll
        for (int off = 16; off; off >>= 1)
            s += __shfl_xor_sync(0xffffffffu, s, off);
        if (lane == 0) {
            unsigned b = __float_as_uint(s);
            g_keysA[warpId] = (b & 0x80000000u) ? ~b : (b | 0x80000000u);
        }
    }
    if (gtid < NPAD - N) g_keysA[N + gtid] = 0xFFFFFFFFu;
}

// ---------------------------------------------------------------------------
// 2) Radix sort: 4 passes x 8 bits
// ---------------------------------------------------------------------------
__global__ void hist_kernel(int srcIsA, int shift, int NB)
{
    const unsigned* in = srcIsA ? g_keysA : g_keysB;
    __shared__ unsigned sh[256];
    sh[threadIdx.x] = 0;
    __syncthreads();
    unsigned key = in[blockIdx.x * 256 + threadIdx.x];
    atomicAdd(&sh[(key >> shift) & 255u], 1u);
    __syncthreads();
    g_hist[threadIdx.x * NB + blockIdx.x] = sh[threadIdx.x];
}

__global__ void scan_digit_kernel(int NB)
{
    int d = blockIdx.x;
    int t = threadIdx.x;
    __shared__ unsigned sh[256];
    __shared__ unsigned s_tot;
    unsigned carry = 0;
    for (int base = 0; base < NB; base += 256) {
        int i = base + t;
        unsigned v = (i < NB) ? g_hist[d * NB + i] : 0u;
        sh[t] = v;
        __syncthreads();
        unsigned x = v;
        #pragma unroll
        for (int off = 1; off < 256; off <<= 1) {
            unsigned y = (t >= off) ? sh[t - off] : 0u;
            __syncthreads();
            if (t >= off) x += y;
            sh[t] = x;
            __syncthreads();
        }
        if (i < NB) g_prefix[d * NB + i] = carry + x - v;
        if (t == 255) s_tot = x;
        __syncthreads();
        carry += s_tot;
        __syncthreads();
    }
    if (t == 0) g_digitTotal[d] = carry;
}

__global__ void scan_base_kernel()
{
    int t = threadIdx.x;
    __shared__ unsigned sh[256];
    unsigned v = g_digitTotal[t];
    sh[t] = v;
    __syncthreads();
    unsigned x = v;
    #pragma unroll
    for (int off = 1; off < 256; off <<= 1) {
        unsigned y = (t >= off) ? sh[t - off] : 0u;
        __syncthreads();
        if (t >= off) x += y;
        sh[t] = x;
        __syncthreads();
    }
    g_digitBase[t] = x - v;
}

__global__ void scatter_kernel(int srcIsA, int shift, int NB)
{
    const unsigned* in  = srcIsA ? g_keysA : g_keysB;
    unsigned*       out = srcIsA ? g_keysB : g_keysA;
    __shared__ unsigned warpHist[8][256];
    int t = threadIdx.x, w = t >> 5, lane = t & 31;
    for (int i = t; i < 8 * 256; i += 256) ((unsigned*)warpHist)[i] = 0u;
    __syncthreads();

    unsigned key = in[blockIdx.x * 256 + t];
    unsigned d   = (key >> shift) & 255u;
    unsigned peers = __match_any_sync(0xffffffffu, d);
    unsigned rank  = __popc(peers & ((1u << lane) - 1u));
    int leader = __ffs(peers) - 1;
    if (lane == leader) warpHist[w][d] = __popc(peers);
    __syncthreads();

    unsigned base = 0;
    for (int w2 = 0; w2 < w; ++w2) base += warpHist[w2][d];
    unsigned pos = g_digitBase[d] + g_prefix[d * NB + blockIdx.x] + base + rank;
    out[pos] = key;
}

// ---------------------------------------------------------------------------
// 3) Finalize: inverse key transform, store sorted doubles 1-based in g_xs
// ---------------------------------------------------------------------------
__global__ void finalize_kernel(int N)
{
    int i = blockIdx.x * blockDim.x + threadIdx.x;
    if (i == 0) g_xs[0] = 0.0;
    if (i < N) {
        unsigned k = g_keysA[i];
        unsigned b = (k & 0x80000000u) ? (k ^ 0x80000000u) : ~k;
        g_xs[i + 1] = (double)__uint_as_float(b);
    }
}

__global__ void dip_init_kernel(float* out, int N)
{
    g_low = 1; g_high = N; g_dip = 1.0;
    g_done = (N < 4 || g_xs[1] == g_xs[N]) ? 1 : 0;
    out[0] = (float)(1.0 / (2.0 * (double)(N > 1 ? N : 1)));
}

// ---------------------------------------------------------------------------
// Graham push with the exact reference pop predicate:
// pop top t (below b) for new point c when NOT [(x_c-x_t)(t-b) < (x_t-x_b)(c-t)].
// Works for both lower hull (ascending idx) and upper hull (descending idx).
// ---------------------------------------------------------------------------
__device__ __forceinline__ void graham_push(int* st, int& sp, int idx, double x)
{
    while (sp >= 2) {
        int t = st[sp - 1], b = st[sp - 2];
        double xt = g_xs[t], xb = g_xs[b];
        if ((x - xt) * (double)(t - b) < (xt - xb) * (double)(idx - t)) break;
        --sp;
    }
    st[sp++] = idx;
}

// ---------------------------------------------------------------------------
// kA: level-1 chunk hulls. 2048 chunks per hull; blocks 0..7 lower, 8..15 upper.
// Lower hull domain: indices [1..high] ascending. Upper: [low..N] descending.
// ---------------------------------------------------------------------------
__global__ void hull_l1_kernel(int N)
{
    if (g_done) return;
    int gt = blockIdx.x * blockDim.x + threadIdx.x;
    int upper = (gt >= CHUNKS);
    int c = upper ? gt - CHUNKS : gt;
    if (c >= CHUNKS) return;

    int low = g_low, high = g_high;
    int M = upper ? (N - low + 1) : high;
    int cs = (M + CHUNKS - 1) / CHUNKS;
    long p0 = (long)c * cs;
    long p1 = p0 + cs; if (p1 > M) p1 = M;

    int* st = (upper ? g_candUp : g_candLo) + (size_t)c * CAP;
    int sp = 0;
    for (long p = p0; p < p1; ++p) {
        int idx = upper ? (N - (int)p) : (1 + (int)p);
        graham_push(st, sp, idx, g_xs[idx]);
    }
    (upper ? g_candCntUp : g_candCntLo)[c] = sp;
}

// ---------------------------------------------------------------------------
// kB: merge chunk hulls (L2: 32 groups/hull, L3: sequential), build gcm/lcm
// chains in reference layout, run the zigzag, precompute per-segment C.
// ---------------------------------------------------------------------------
__global__ void __launch_bounds__(1024, 1) merge_kernel(int N)
{
    if (g_done) return;
    int tid = threadIdx.x;
    __shared__ int s_mLo, s_mUp;
    __shared__ int s_ig, s_ih, s_lg, s_ll;

    // --- L2: each of 64 threads merges 64 chunk candidate lists ---
    if (tid < 2 * L2GROUPS) {
        int upper = (tid >= L2GROUPS);
        int g = upper ? tid - L2GROUPS : tid;
        const int* cand = upper ? g_candUp : g_candLo;
        const int* cnt  = upper ? g_candCntUp : g_candCntLo;
        int* out = (upper ? g_l2Up : g_l2Lo) + (size_t)g * L2STRIDE;
        int sp = 0;
        for (int c = g * CHPERGRP; c < (g + 1) * CHPERGRP; ++c) {
            int n = cnt[c];
            const int* src = cand + (size_t)c * CAP;
            for (int k = 0; k < n; ++k) {
                int idx = src[k];
                graham_push(out, sp, idx, g_xs[idx]);
            }
        }
        (upper ? g_l2CntUp : g_l2CntLo)[g] = sp;
    }
    __syncthreads();

    // --- L3: final sequential merges (two concurrent warps) ---
    if (tid == 0) {
        int sp = 0;
        for (int g = 0; g < L2GROUPS; ++g) {
            int n = g_l2CntLo[g];
            const int* src = g_l2Lo + (size_t)g * L2STRIDE;
            for (int k = 0; k < n; ++k) {
                int idx = src[k];
                graham_push(g_hullLo, sp, idx, g_xs[idx]);
            }
        }
        s_mLo = sp;
    } else if (tid == 32) {
        int sp = 0;
        for (int g = 0; g < L2GROUPS; ++g) {
            int n = g_l2CntUp[g];
            const int* src = g_l2Up + (size_t)g * L2STRIDE;
            for (int k = 0; k < n; ++k) {
                int idx = src[k];
                graham_push(g_hullUp, sp, idx, g_xs[idx]);
            }
        }
        s_mUp = sp;
    }
    __syncthreads();

    // --- chains + zigzag on thread 0 ---
    if (tid == 0) {
        const double* xs = g_xs;
        int low = g_low, high = g_high;

        // gcm: descending from high (hullLo ascending, last element == high),
        // stop at first vertex <= low  (hullLo[0] == 1 guarantees termination)
        {
            int k = s_mLo - 1, i = 1;
            while (true) {
                int v = g_hullLo[k];
                g_gcm[i] = v;
                if (v <= low) break;
                --k; ++i;
            }
            s_lg = i;
        }
        // lcm: ascending from low (hullUp descending, last element == low),
        // stop at first vertex >= high (hullUp[0] == N guarantees termination)
        {
            int k = s_mUp - 1, i = 1;
            while (true) {
                int v = g_hullUp[k];
                g_lcm[i] = v;
                if (v >= high) break;
                --k; ++i;
            }
            s_ll = i;
        }

        int l_gcm = s_lg, l_lcm = s_ll;
        int ig = l_gcm, ih = l_lcm;
        int ix = l_gcm - 1, iv = 2;
        double d = 0.0;
        if (l_gcm != 2 || l_lcm != 2) {
            while (true) {
                int gcmix = g_gcm[ix], lcmiv = g_lcm[iv];
                if (gcmix > lcmiv) {
                    int gcmi1 = g_gcm[ix + 1];
                    double t = ((double)lcmiv - (double)gcmi1 + 1.0)
                             - (xs[lcmiv] - xs[gcmi1]) * (double)(gcmix - gcmi1)
                               / (xs[gcmix] - xs[gcmi1]);
                    ++iv;
                    if (t >= d) { d = t; ig = ix + 1; ih = iv - 1; }
                } else {
                    int lcmiv1 = g_lcm[iv - 1];
                    double t = (xs[gcmix] - xs[lcmiv1]) * (double)(lcmiv - lcmiv1)
                               / (xs[lcmiv] - xs[lcmiv1])
                             - ((double)gcmix - (double)lcmiv1 - 1.0);
                    --ix;
                    if (t > d) { d = t; ig = ix + 1; ih = iv; }
                }
                if (ix < 1) ix = 1;
                if (iv > l_lcm) iv = l_lcm;
                if (g_gcm[ix] == g_lcm[iv]) break;
            }
        } else {
            d = 1.0;
        }
        s_ig = ig; s_ih = ih;
        g_ig = ig; g_ih = ih; g_lgcm = l_gcm; g_llcm = l_lcm;
        g_scanmax = 0ull;
        if (d < g_dip) g_done = 1;
    }
    __syncthreads();
    if (g_done) return;

    // --- per-segment slope C precompute (parallel) ---
    int ig = s_ig, ih = s_ih, lg = s_lg, ll = s_ll;
    for (int j = ig + tid; j < lg; j += 1024) {
        int jb = g_gcm[j + 1], je = g_gcm[j];
        double C = 0.0;
        if (je - jb > 1 && g_xs[je] != g_xs[jb])
            C = (double)(je - jb) / (g_xs[je] - g_xs[jb]);
        g_segCLo[j] = C;
    }
    for (int j = ih + tid; j < ll; j += 1024) {
        int jb = g_lcm[j], je = g_lcm[j + 1];
        double C = 0.0;
        if (je - jb > 1 && g_xs[je] != g_xs[jb])
            C = (double)(je - jb) / (g_xs[je] - g_xs[jb]);
        g_segCUp[j] = C;
    }
}

// ---------------------------------------------------------------------------
// kC: grid-wide segment max scan -> atomicMax(g_scanmax)
// ---------------------------------------------------------------------------
__global__ void scan_seg_kernel()
{
    if (g_done) return;
    int ig = g_ig, ih = g_ih, lg = g_lgcm, ll = g_llcm;

    long cntLo = 0, cntUp = 0;
    int loA = 0, upA = 0;
    if (ig < lg) { loA = g_gcm[lg]; cntLo = (long)g_gcm[ig] - loA + 1; }
    if (ih < ll) { upA = g_lcm[ih]; cntUp = (long)g_lcm[ll] - upA + 1; }
    long tot = cntLo + cntUp;

    double local = 0.0;
    long stride = (long)gridDim.x * blockDim.x;
    for (long e = (long)blockIdx.x * blockDim.x + threadIdx.x; e < tot; e += stride) {
        if (e < cntLo) {
            int i = loA + (int)e;
            // smallest j in [ig, lg-1] with gcm[j+1] <= i
            int a = ig, b = lg - 1;
            while (a < b) { int m = (a + b) >> 1; if (g_gcm[m + 1] <= i) b = m; else a = m + 1; }
            double C = g_segCLo[a];
            if (C != 0.0) {
                int jb = g_gcm[a + 1];
                double t = (double)(i - jb + 1) - (g_xs[i] - g_xs[jb]) * C;
                if (t > local) local = t;
            }
        } else {
            int i = upA + (int)(e - cntLo);
            // largest j in [ih, ll-1] with lcm[j] <= i
            int a = ih, b = ll - 1;
            while (a < b) { int m = (a + b + 1) >> 1; if (g_lcm[m] <= i) a = m; else b = m - 1; }
            double C = g_segCUp[a];
            if (C != 0.0) {
                int jb = g_lcm[a];
                double t = (g_xs[i] - g_xs[jb]) * C - (double)(i - jb - 1);
                if (t > local) local = t;
            }
        }
    }

    __shared__ double red[256];
    int t = threadIdx.x;
    red[t] = local;
    __syncthreads();
    #pragma unroll
    for (int off = 128; off >= 1; off >>= 1) {
        if (t < off) { double o = red[t + off]; if (o > red[t]) red[t] = o; }
        __syncthreads();
    }
    if (t == 0 && red[0] > 1.0)
        atomicMax(&g_scanmax, (unsigned long long)__double_as_longlong(red[0]));
}

// ---------------------------------------------------------------------------
// kD: scalar update of dip / low / high / done, write output
// ---------------------------------------------------------------------------
__global__ void update_kernel(float* out, int N)
{
    if (g_done) return;
    double dip = g_dip;
    double sm = __longlong_as_double((long long)g_scanmax);
    if (sm > dip) dip = sm;
    g_dip = dip;
    out[0] = (float)(dip / (2.0 * (double)N));
    int nlow = g_gcm[g_ig], nhigh = g_lcm[g_ih];
    if (nlow == g_low && nhigh == g_high) {
        g_done = 1;
    } else {
        g_low = nlow; g_high = nhigh;
    }
}

// ---------------------------------------------------------------------------
// kernel_launch
// ---------------------------------------------------------------------------
extern "C" void kernel_launch(void* const* d_in, const int* in_sizes, int n_in,
                              void* d_out, int out_size)
{
    const float* X   = (const float*)d_in[0];
    const float* P   = (const float*)d_in[1];
    const int*   idx = (const int*)d_in[2];
    float*       out = (float*)d_out;

    int N    = in_sizes[0] / DDIM;
    int NB   = (N + 255) / 256;
    int NPAD = NB * 256;

    // 1) projection + key transform + padding
    proj_kernel<<<(N + 7) / 8, 256>>>(X, P, idx, N, NPAD);

    // 2) radix sort, 4 passes of 8 bits (A->B->A->B->A)
    int srcIsA = 1;
    for (int pass = 0; pass < 4; ++pass) {
        int shift = pass * 8;
        hist_kernel<<<NB, 256>>>(srcIsA, shift, NB);
        scan_digit_kernel<<<256, 256>>>(NB);
        scan_base_kernel<<<1, 256>>>();
        scatter_kernel<<<NB, 256>>>(srcIsA, shift, NB);
        srcIsA ^= 1;
    }

    // 3) sorted keys -> double xs[1..N], init dip state
    finalize_kernel<<<(N + 255) / 256, 256>>>(N);
    dip_init_kernel<<<1, 1>>>(out, N);

    // 4) dip outer loop, unrolled to MAXIT device-gated iterations
    for (int it = 0; it < MAXIT; ++it) {
        hull_l1_kernel<<<(2 * CHUNKS) / 256, 256>>>(N);
        merge_kernel<<<1, 1024>>>(N);
        scan_seg_kernel<<<96, 256>>>();
        update_kernel<<<1, 1>>>(out, N);
    }
}